// round 14
// baseline (speedup 1.0000x reference)
#include <cuda_runtime.h>

// Problem constants
#define Hdim 512
#define Bdim 256
#define Tdim 1024
#define NCLS 10

// Geometry: 128 CTAs = 8 row-groups x 16 col-groups, 256 threads each.
// All h traffic is column-group-local -> 16 independent 8-way barriers.
// Warps are K-SPLIT: each warp computes the full 64x16 output tile for a
// 64-wide k-slice; partials reduced through a smem slab.
// R14: h is read DIRECTLY from L2 inside the FMA loop (no smem staging --
// each h value is consumed once per warp, staging bought nothing), and the
// tanh uses the MUFU EX2/RCP path instead of libm tanhf.
#define NCTA 128
#define TPB  256
#define NCG  16        // column groups
#define NRG  8         // row groups (CTAs per barrier group)
#define HR 64          // rows of h computed per CTA
#define BC 16          // batch columns per CTA
#define PW 516         // smem pitch (floats): 16B-aligned rows, conflict-free
#define SLAB_PITCH 33              // conflict-free scalar slab
#define SLAB_WSTRIDE (32 * SLAB_PITCH)   // 1056 floats per warp
#define SMEM_FLOATS (HR * PW + 8 * SLAB_WSTRIDE + 16)
#define SMEM_BYTES (SMEM_FLOATS * 4)     // ~166 KB

// Persistent state: double-buffered hidden state, TRANSPOSED: hT[b][k].
__device__ float g_hT[2][Bdim * Hdim];
// One barrier counter per column group, padded to 128B lines.
__device__ unsigned int g_bar[NCG * 32];

// Packed fp32x2 FMA (Blackwell): 2 FMA per instruction on the fma pipe.
__device__ __forceinline__ void fma2(unsigned long long& acc,
                                     unsigned long long a,
                                     unsigned long long b) {
    asm("fma.rn.f32x2 %0, %1, %2, %0;" : "+l"(acc) : "l"(a), "l"(b));
}

// Fast tanh on the MUFU path: ~1e-7 rel error (safe for the recurrence,
// unlike tanh.approx.f32 whose 5e-4 error would accumulate past 1e-3).
__device__ __forceinline__ float tanh_fast(float v) {
    float y = fminf(fmaxf(v, -10.0f), 10.0f);
    float e = __expf(2.0f * y);                 // MUFU.EX2 path
    return __fdividef(e - 1.0f, e + 1.0f);      // MUFU.RCP path
}

__global__ void __launch_bounds__(TPB, 1)
rnn_persistent(const float* __restrict__ x,       // [B, T]
               const float* __restrict__ h_init,  // [H]
               const float* __restrict__ W_hx,    // [H]
               const float* __restrict__ W_hh,    // [H, H]
               const float* __restrict__ b_h,     // [H]
               const float* __restrict__ W_ph,    // [NCLS, H]
               const float* __restrict__ b_p,     // [NCLS]
               float* __restrict__ out)           // [B, NCLS]
{
    extern __shared__ float smem[];
    float* sW = smem;                 // [HR][PW]  W_hh row-slice
    float* sP = sW + HR * PW;         // [8][32][33] partial slab
    float* sX = sP + 8 * SLAB_WSTRIDE;// [16] x values for this step

    const int cta = blockIdx.x;
    const int tid = threadIdx.x;
    const int cg  = cta & (NCG - 1);     // column group -> barrier group
    const int rg  = cta >> 4;            // row group
    const int rBase = rg * HR;
    const int cBase = cg * BC;

    volatile unsigned int* barp = &g_bar[cg * 32];

    // ---- One-time: load W_hh slice (rows rBase..rBase+HR) into smem ----
    for (int i = tid; i < HR * (Hdim / 4); i += TPB) {
        int r  = i >> 7;          // Hdim/4 == 128
        int k4 = i & 127;
        float4 v = reinterpret_cast<const float4*>(W_hh + (rBase + r) * Hdim)[k4];
        *reinterpret_cast<float4*>(sW + r * PW + (k4 << 2)) = v;
    }

    // ---- One-time: init hT buffer 0 with broadcast h_init (GROUP-LOCAL) ----
    {
        float* dst = &g_hT[0][(cBase + 2 * rg) * Hdim];
        for (int i = tid; i < 2 * Hdim; i += TPB)
            __stcg(&dst[i], h_init[i & (Hdim - 1)]);
    }

    // ---- Warp/lane mapping (k-split) ----
    const int lane = tid & 31;
    const int wrp  = tid >> 5;           // warp = k-slice [wrp*64, wrp*64+64)
    const int lr   = lane >> 2;          // 0..7: rows lr + 8*i (i=0..7)
    const int lc   = lane & 3;           // 0..3: cols lc + 4*j (j=0..3)
    const int wk   = wrp * 64;           // k base for this warp

    const float* wbase = sW + lr * PW + wk;
    float* myslab = sP + wrp * SLAB_WSTRIDE + lane * SLAB_PITCH;
    // Per-lane global h column bases (element offsets within a buffer).
    const int hoff0 = (cBase + lc +  0) * Hdim + wk;
    const int hoff1 = (cBase + lc +  4) * Hdim + wk;
    const int hoff2 = (cBase + lc +  8) * Hdim + wk;
    const int hoff3 = (cBase + lc + 12) * Hdim + wk;

    // ---- Reduction-thread mapping: thread tid owns outputs (rr, 4*cq+m) ----
    const int rr  = tid >> 2;            // 0..63
    const int cq  = tid & 3;             // col quarter
    const float whx_r = W_hx[rBase + rr];
    const float bh_r  = b_h[rBase + rr];
    const int   slot  = (rr >> 3) * 4 + cq;       // fixed slab slot
    const float* rdslab = sP + ((rr & 7) * 4) * SLAB_PITCH + slot;

    unsigned int target = NRG;

    // Column-group barrier: 8 arrivals on a private counter.
#define GROUP_SYNC()                                                  \
    do {                                                              \
        __threadfence();                                              \
        __syncthreads();                                              \
        if (tid == 0) {                                               \
            atomicAdd((unsigned int*)barp, 1u);                       \
            while (*barp < target) { }                                \
            __threadfence();                                          \
        }                                                             \
        __syncthreads();                                              \
        target += NRG;                                                \
    } while (0)

    GROUP_SYNC();   // W slice + h0 init visible inside the group

    for (int t = 0; t < Tdim; t++) {
        const float* hc = g_hT[t & 1];
        float*       hn = g_hT[(t + 1) & 1];

        // Stage this step's 16 x values into smem (read after the slab sync).
        if (tid < BC)
            sX[tid] = __ldcg(&x[(cBase + tid) * Tdim + t]);

        const longlong2* hg0 = reinterpret_cast<const longlong2*>(hc + hoff0);
        const longlong2* hg1 = reinterpret_cast<const longlong2*>(hc + hoff1);
        const longlong2* hg2 = reinterpret_cast<const longlong2*>(hc + hoff2);
        const longlong2* hg3 = reinterpret_cast<const longlong2*>(hc + hoff3);

        // ---- Compute: per lane 8 rows x 4 cols over a 64-wide k slice.
        // W from smem (broadcast across lc), h straight from L2 (broadcast
        // across lr; 4 distinct 16B per LDG -> L2 dedup handles it).
        unsigned long long acc[8][4];
#pragma unroll
        for (int i = 0; i < 8; i++)
#pragma unroll
            for (int j = 0; j < 4; j++) acc[i][j] = 0ull;

#pragma unroll 4
        for (int k4 = 0; k4 < 16; k4++) {
            longlong2 lh[4];
            lh[0] = __ldcg(hg0 + k4);
            lh[1] = __ldcg(hg1 + k4);
            lh[2] = __ldcg(hg2 + k4);
            lh[3] = __ldcg(hg3 + k4);
            longlong2 lw[8];
#pragma unroll
            for (int i = 0; i < 8; i++)
                lw[i] = *reinterpret_cast<const longlong2*>(wbase + i * 8 * PW + (k4 << 2));
#pragma unroll
            for (int i = 0; i < 8; i++)
#pragma unroll
                for (int j = 0; j < 4; j++) {
                    fma2(acc[i][j], (unsigned long long)lw[i].x, (unsigned long long)lh[j].x);
                    fma2(acc[i][j], (unsigned long long)lw[i].y, (unsigned long long)lh[j].y);
                }
        }

        // ---- Fold f32x2 pairs and store partials (conflict-free STS.32) ----
#pragma unroll
        for (int i = 0; i < 8; i++)
#pragma unroll
            for (int j = 0; j < 4; j++) {
                float2 a = *reinterpret_cast<float2*>(&acc[i][j]);
                myslab[i * 4 + j] = a.x + a.y;
            }
        __syncthreads();

        // ---- Reduce 8 k-partials, add input/bias, tanh, store h ----
#pragma unroll
        for (int m = 0; m < 4; m++) {
            const float* p = rdslab + m * SLAB_PITCH;
            float s = p[0];
#pragma unroll
            for (int w = 1; w < 8; w++) s += p[w * SLAB_WSTRIDE];
            int c = 4 * cq + m;
            float val = tanh_fast(s + whx_r * sX[c] + bh_r);
            __stcg(&hn[(cBase + c) * Hdim + rBase + rr], val);
        }

        GROUP_SYNC();   // release h stores to group peers; guards sP/sX reuse
    }

    // ---- Final projection (group-local batch columns).
    // T even -> h_last lives in g_hT[0], layout [B][H] (contiguous dot).
    if (tid < 20) {
        const int o  = rg * 20 + tid;            // 0..159 within group
        const int b  = cBase + o / NCLS;
        const int n  = o % NCLS;
        const float* wr = W_ph + n * Hdim;
        const float* hf = g_hT[0] + b * Hdim;
        float s = b_p[n];
#pragma unroll 4
        for (int k4 = 0; k4 < Hdim / 4; k4++) {
            float4 w = reinterpret_cast<const float4*>(wr)[k4];
            float4 h = __ldcg(reinterpret_cast<const float4*>(hf) + k4);
            s += w.x * h.x + w.y * h.y + w.z * h.z + w.w * h.w;
        }
        out[b * NCLS + n] = s;
    }
#undef GROUP_SYNC
}

extern "C" void kernel_launch(void* const* d_in, const int* in_sizes, int n_in,
                              void* d_out, int out_size) {
    const float* x      = (const float*)d_in[0];
    const float* h_init = (const float*)d_in[1];
    const float* W_hx   = (const float*)d_in[2];
    const float* W_hh   = (const float*)d_in[3];
    const float* b_h    = (const float*)d_in[4];
    const float* W_ph   = (const float*)d_in[5];
    const float* b_p    = (const float*)d_in[6];
    float* out = (float*)d_out;

    cudaFuncSetAttribute(rnn_persistent,
                         cudaFuncAttributeMaxDynamicSharedMemorySize, SMEM_BYTES);

    // Reset the barrier counters every launch (graph-capturable, no allocs).
    void* barp = nullptr;
    cudaGetSymbolAddress(&barp, g_bar);
    cudaMemsetAsync(barp, 0, NCG * 32 * sizeof(unsigned int), 0);

    rnn_persistent<<<NCTA, TPB, SMEM_BYTES, 0>>>(x, h_init, W_hx, W_hh,
                                                 b_h, W_ph, b_p, out);
}

// round 15
// speedup vs baseline: 1.2880x; 1.2880x over previous
#include <cuda_runtime.h>

// Problem constants
#define Hdim 512
#define Bdim 256
#define Tdim 1024
#define NCLS 10

// Geometry: 128 CTAs = 8 row-groups x 16 col-groups, 256 threads each.
// Batch columns are independent RNNs; h exchange is column-group-local ->
// 16 independent 8-CTA barrier groups (distributed versioned flags).
// Warps are K-SPLIT: each warp computes the full 64x16 output tile for a
// 64-wide k-slice; partials reduced through a smem slab. (R13 structure.)
// R15: MUFU-path tanh (validated in R14) + flag-based group barrier.
#define NCTA 128
#define TPB  256
#define NCG  16        // column groups
#define NRG  8         // row groups (CTAs per barrier group)
#define HR 64          // rows of h computed per CTA
#define BC 16          // batch columns per CTA
#define PW 516         // smem pitch (floats): 16B-aligned rows, conflict-free
#define PH 516
#define SLAB_PITCH 33              // conflict-free scalar slab
#define SLAB_WSTRIDE (32 * SLAB_PITCH)   // 1056 floats per warp
#define SMEM_FLOATS (HR * PW + BC * PH + 8 * SLAB_WSTRIDE + 16)
#define SMEM_BYTES (SMEM_FLOATS * 4)     // 198,976 B

// Persistent state: double-buffered hidden state, TRANSPOSED: hT[b][k].
__device__ float g_hT[2][Bdim * Hdim];
// Distributed barrier flags: one per (group, row-group), each on its own
// 128B line. Versioned (monotone step count) -> never reset, no ABA.
__device__ volatile unsigned int g_flag[NCG * NRG * 32];

// Packed fp32x2 FMA (Blackwell): 2 FMA per instruction on the fma pipe.
__device__ __forceinline__ void fma2(unsigned long long& acc,
                                     unsigned long long a,
                                     unsigned long long b) {
    asm("fma.rn.f32x2 %0, %1, %2, %0;" : "+l"(acc) : "l"(a), "l"(b));
}

// Fast tanh on the MUFU path (~1e-7 rel err; validated R14: final 1.6e-6).
__device__ __forceinline__ float tanh_fast(float v) {
    float y = fminf(fmaxf(v, -10.0f), 10.0f);
    float e = __expf(2.0f * y);                 // MUFU.EX2 path
    return __fdividef(e - 1.0f, e + 1.0f);      // MUFU.RCP path
}

__global__ void __launch_bounds__(TPB, 1)
rnn_persistent(const float* __restrict__ x,       // [B, T]
               const float* __restrict__ h_init,  // [H]
               const float* __restrict__ W_hx,    // [H]
               const float* __restrict__ W_hh,    // [H, H]
               const float* __restrict__ b_h,     // [H]
               const float* __restrict__ W_ph,    // [NCLS, H]
               const float* __restrict__ b_p,     // [NCLS]
               float* __restrict__ out)           // [B, NCLS]
{
    extern __shared__ float smem[];
    float* sW = smem;                 // [HR][PW]  W_hh row-slice
    float* sH = sW + HR * PW;         // [BC][PH]  hT block: sH[c][k]
    float* sP = sH + BC * PH;         // [8][32][33] partial slab
    float* sX = sP + 8 * SLAB_WSTRIDE;// [16] x values for this step

    const int cta = blockIdx.x;
    const int tid = threadIdx.x;
    const int cg  = cta & (NCG - 1);     // column group -> barrier group
    const int rg  = cta >> 4;            // row group
    const int rBase = rg * HR;
    const int cBase = cg * BC;

    // ---- One-time: load W_hh slice (rows rBase..rBase+HR) into smem ----
    for (int i = tid; i < HR * (Hdim / 4); i += TPB) {
        int r  = i >> 7;          // Hdim/4 == 128
        int k4 = i & 127;
        float4 v = reinterpret_cast<const float4*>(W_hh + (rBase + r) * Hdim)[k4];
        *reinterpret_cast<float4*>(sW + r * PW + (k4 << 2)) = v;
    }

    // ---- One-time: init hT buffer 0 with broadcast h_init (GROUP-LOCAL) ----
    {
        float* dst = &g_hT[0][(cBase + 2 * rg) * Hdim];
        for (int i = tid; i < 2 * Hdim; i += TPB)
            __stcg(&dst[i], h_init[i & (Hdim - 1)]);
    }

    // ---- Warp/lane mapping (k-split) ----
    const int lane = tid & 31;
    const int wrp  = tid >> 5;           // warp = k-slice [wrp*64, wrp*64+64)
    const int lr   = lane >> 2;          // 0..7: rows lr + 8*i (i=0..7)
    const int lc   = lane & 3;           // 0..3: cols lc + 4*j (j=0..3)
    const int wk   = wrp * 64;           // k base for this warp

    const float* wbase = sW + lr * PW + wk;
    const float* hbase = sH + lc * PH + wk;
    float* myslab = sP + wrp * SLAB_WSTRIDE + lane * SLAB_PITCH;

    // ---- Reduction-thread mapping: thread tid owns outputs (rr, 4*cq+m) ----
    const int rr  = tid >> 2;            // 0..63
    const int cq  = tid & 3;             // col quarter
    const float whx_r = W_hx[rBase + rr];
    const float bh_r  = b_h[rBase + rr];
    const int   slot  = (rr >> 3) * 4 + cq;       // fixed slab slot
    const float* rdslab = sP + ((rr & 7) * 4) * SLAB_PITCH + slot;

    // Distributed-flag group barrier:
    //   all threads fence -> __syncthreads (orders everyone's h stores before
    //   tid0's flag store) -> tid0 publishes version -> tids 0..7 each poll
    //   one peer flag in parallel -> acquire fence -> __syncthreads.
    volatile unsigned int* myflag = &g_flag[(cg * NRG + rg) * 32];
    volatile unsigned int* gflags = &g_flag[cg * NRG * 32];
    unsigned int ver = 1;

#define GROUP_SYNC()                                                  \
    do {                                                              \
        __threadfence();                                              \
        __syncthreads();                                              \
        if (tid == 0) *myflag = ver;                                  \
        if (tid < NRG) {                                              \
            while (gflags[tid * 32] < ver) { }                        \
            __threadfence();                                          \
        }                                                             \
        __syncthreads();                                              \
        ver++;                                                        \
    } while (0)

    GROUP_SYNC();   // W slice + h0 init visible inside the group

    for (int t = 0; t < Tdim; t++) {
        const float* hc = g_hT[t & 1];
        float*       hn = g_hT[(t + 1) & 1];

        // Stage this step's 16 x values into smem.
        if (tid < BC)
            sX[tid] = __ldcg(&x[(cBase + tid) * Tdim + t]);

        // Load the group's hT block: 16 rows x 512 floats, coalesced LDG.128
        // + aligned STS.128 (one L2 round trip, amortized by the whole loop).
        for (int i = tid; i < BC * (Hdim / 4); i += TPB) {
            int cc = i >> 7;          // Hdim/4 == 128
            int k4 = i & 127;
            float4 v = __ldcg(reinterpret_cast<const float4*>(hc + (cBase + cc) * Hdim) + k4);
            *reinterpret_cast<float4*>(sH + cc * PH + (k4 << 2)) = v;
        }
        __syncthreads();

        // ---- Compute: per lane 8 rows x 4 cols over a 64-wide k slice ----
        unsigned long long acc[8][4];
#pragma unroll
        for (int i = 0; i < 8; i++)
#pragma unroll
            for (int j = 0; j < 4; j++) acc[i][j] = 0ull;

#pragma unroll 2
        for (int k4 = 0; k4 < 16; k4++) {
            longlong2 lw[8];
            longlong2 lh[4];
#pragma unroll
            for (int i = 0; i < 8; i++)
                lw[i] = *reinterpret_cast<const longlong2*>(wbase + i * 8 * PW + (k4 << 2));
#pragma unroll
            for (int j = 0; j < 4; j++)
                lh[j] = *reinterpret_cast<const longlong2*>(hbase + j * 4 * PH + (k4 << 2));
#pragma unroll
            for (int i = 0; i < 8; i++)
#pragma unroll
                for (int j = 0; j < 4; j++) {
                    fma2(acc[i][j], (unsigned long long)lw[i].x, (unsigned long long)lh[j].x);
                    fma2(acc[i][j], (unsigned long long)lw[i].y, (unsigned long long)lh[j].y);
                }
        }

        // ---- Fold f32x2 pairs and store partials (conflict-free STS.32) ----
#pragma unroll
        for (int i = 0; i < 8; i++)
#pragma unroll
            for (int j = 0; j < 4; j++) {
                float2 a = *reinterpret_cast<float2*>(&acc[i][j]);
                myslab[i * 4 + j] = a.x + a.y;
            }
        __syncthreads();

        // ---- Reduce 8 k-partials, add input/bias, tanh, store h ----
#pragma unroll
        for (int m = 0; m < 4; m++) {
            const float* p = rdslab + m * SLAB_PITCH;
            float s = p[0];
#pragma unroll
            for (int w = 1; w < 8; w++) s += p[w * SLAB_WSTRIDE];
            int c = 4 * cq + m;
            float val = tanh_fast(s + whx_r * sX[c] + bh_r);
            __stcg(&hn[(cBase + c) * Hdim + rBase + rr], val);
        }

        GROUP_SYNC();   // release h stores to group peers; guards sH/sP reuse
    }

    // ---- Final projection (group-local batch columns).
    // T even -> h_last lives in g_hT[0], layout [B][H] (contiguous dot).
    if (tid < 20) {
        const int o  = rg * 20 + tid;            // 0..159 within group
        const int b  = cBase + o / NCLS;
        const int n  = o % NCLS;
        const float* wr = W_ph + n * Hdim;
        const float* hf = g_hT[0] + b * Hdim;
        float s = b_p[n];
#pragma unroll 4
        for (int k4 = 0; k4 < Hdim / 4; k4++) {
            float4 w = reinterpret_cast<const float4*>(wr)[k4];
            float4 h = __ldcg(reinterpret_cast<const float4*>(hf) + k4);
            s += w.x * h.x + w.y * h.y + w.z * h.z + w.w * h.w;
        }
        out[b * NCLS + n] = s;
    }
#undef GROUP_SYNC
}

extern "C" void kernel_launch(void* const* d_in, const int* in_sizes, int n_in,
                              void* d_out, int out_size) {
    const float* x      = (const float*)d_in[0];
    const float* h_init = (const float*)d_in[1];
    const float* W_hx   = (const float*)d_in[2];
    const float* W_hh   = (const float*)d_in[3];
    const float* b_h    = (const float*)d_in[4];
    const float* W_ph   = (const float*)d_in[5];
    const float* b_p    = (const float*)d_in[6];
    float* out = (float*)d_out;

    cudaFuncSetAttribute(rnn_persistent,
                         cudaFuncAttributeMaxDynamicSharedMemorySize, SMEM_BYTES);

    // Reset the barrier flags every launch (graph-capturable, no allocs).
    void* flagp = nullptr;
    cudaGetSymbolAddress(&flagp, g_flag);
    cudaMemsetAsync(flagp, 0, NCG * NRG * 32 * sizeof(unsigned int), 0);

    rnn_persistent<<<NCTA, TPB, SMEM_BYTES, 0>>>(x, h_init, W_hx, W_hh,
                                                 b_h, W_ph, b_p, out);
}